// round 16
// baseline (speedup 1.0000x reference)
#include <cuda_runtime.h>
#include <math.h>

// DTW 2048x2048, 2-CTA x 8-warp skewed anti-diagonal block pipeline.
//
// R15 vs R12 (same skeleton: C=2, NT=256, NW=8, RPT=4, BD=32, one
// __syncthreads per step):
//  1. Handoff stores are no longer volatile-generic. Smem handoff = plain
//     STS (ordered by __syncthreads' STS drain); gmem handoff = st.global.cg
//     (consumer validates per element, order irrelevant). R12's volatile
//     generic store acted as a per-diagonal scheduling fence.
//  2. Shfl software pipelining: cell k=RPT-1 (independent of the neighbor
//     value) is computed first, the shfl for the NEXT diagonal issues
//     immediately after it, and the remaining cells fill its 26-cy shadow.
//  3. Inter-CTA prefetch depth 2 (e/en/en2) so CTA clock drift of up to
//     2 steps never exposes the sentinel poll.
//
// Recap: thread t of CTA c owns rows c*1024 + t*4..+3 in registers, b[]/a[]
// roles alternate per diagonal (no rotation MOVs); stage(c,w) = 9c + w;
// warp w computes block q at step s = q + stage; intra-CTA handoff via
// double-buffered smem rows; inter-CTA via data-as-flag sentinel global
// buffer (reset to -1 by a pre-kernel each launch); y padded with BIGV so
// out-of-range cells self-poison.

#define LEN    2048
#define C      2
#define NT     256
#define NW     8
#define RPT    4                  // C*NT*RPT == LEN
#define BD     32                 // diagonals per block
#define NBLK   128                // covers d = 1..4096 (>= 4094)
#define NSTAGE ((C - 1) * (NW + 1) + (NW - 1))   // 16
#define NSTEPS (NBLK + NSTAGE)                   // 144
#define BIGV   1e19f
#define SENT   -1.0f
#define OFF    2047
#define YPSZ   6144

__device__ float g_bound[C][NBLK][BD];

__global__ void reset_bound_kernel()
{
    int i = blockIdx.x * blockDim.x + threadIdx.x;
    if (i < C * NBLK * BD) ((float*)g_bound)[i] = SENT;
}

// Un-hoistable L2 load for the straggler poll.
__device__ __forceinline__ float ld_cg_volatile(const float* p)
{
    float v;
    asm volatile("ld.global.cg.f32 %0, [%1];" : "=f"(v) : "l"(p) : "memory");
    return v;
}
__device__ __forceinline__ void st_cg(float* p, float v)
{
    asm volatile("st.global.cg.f32 [%0], %1;" :: "l"(p), "f"(v));
}

__global__ __launch_bounds__(NT, 1)
void dtw_wavefront(const float* __restrict__ x,
                   const float* __restrict__ y,
                   float* __restrict__ out)
{
    __shared__ float ypad[YPSZ];
    __shared__ float bdry[2][NW][BD];   // [parity][consumer warp][diag]

    const int tid  = threadIdx.x;
    const int lane = tid & 31;
    const int warp = tid >> 5;
    const int cta  = blockIdx.x;

    for (int idx = tid; idx < YPSZ; idx += NT) {
        int j = idx - OFF;
        ypad[idx] = (j >= 0 && j < LEN) ? y[j] : BIGV;
    }
    __syncthreads();

    const int r0 = cta * (NT * RPT) + tid * RPT;

    float xs[RPT];
#pragma unroll
    for (int k = 0; k < RPT; k++) xs[k] = x[r0 + k];

    // State: b = diag d0-1, a = diag d0-2. Only (0,0) finite after diag 0.
    float b[RPT], a[RPT];
#pragma unroll
    for (int k = 0; k < RPT; k++) { b[k] = BIGV; a[k] = BIGV; }
    if (cta == 0 && tid == 0) {
        float c00 = xs[0] - ypad[OFF];
        b[0] = c00 * c00;
    }

    float cb = BIGV, ca = BIGV;     // lane0 carries: upstream bottom b at d0-1, d0-2
    const int  stage = cta * (NW + 1) + warp;
    const bool isl0  = (lane == 0);
    const bool isl31 = (lane == 31);
    const bool wlast = (cta == C - 1 && tid == NT - 1);
    const bool gcons = (warp == 0 && cta > 0);           // global consumer
    const bool sprod = (warp < NW - 1);                  // smem producer
    const bool gprod = (warp == NW - 1 && cta < C - 1);  // gmem producer

    // Upstream boundary: e = block q (validated), en = q+1, en2 = q+2.
    float e[BD], en[BD], en2[BD];
#pragma unroll
    for (int i = 0; i < BD; i++) { e[i] = BIGV; en[i] = BIGV; en2[i] = BIGV; }

    // Prime prefetch: blocks 0 and 1 (unchecked; validated when consumed).
    if (gcons) {
        const float4* g0 = (const float4*)&g_bound[cta - 1][0][0];
        const float4* g1 = (const float4*)&g_bound[cta - 1][1][0];
#pragma unroll
        for (int c4 = 0; c4 < BD / 4; c4++) {
            float4 v0 = __ldcg(g0 + c4);
            e[c4 * 4 + 0] = v0.x; e[c4 * 4 + 1] = v0.y;
            e[c4 * 4 + 2] = v0.z; e[c4 * 4 + 3] = v0.w;
            float4 v1 = __ldcg(g1 + c4);
            en[c4 * 4 + 0] = v1.x; en[c4 * 4 + 1] = v1.y;
            en[c4 * 4 + 2] = v1.z; en[c4 * 4 + 3] = v1.w;
        }
    }

    for (int s = 0; s < NSTEPS; s++) {
        const int q = s - stage;
        const bool active = (q >= 0 && q < NBLK);

        if (active) {
            const int wpar  = s & 1;
            const int rpar  = wpar ^ 1;
            const int d0    = 1 + q * BD;
            const bool qlast = (q == NBLK - 1);

            // ---- obtain boundary e[i] = upstream bottom-row b at diag d0+i ----
            if (warp == 0) {
                if (cta > 0) {
                    // prefetch q+2 (unchecked)
                    if (q + 2 < NBLK) {
                        const float4* gp = (const float4*)&g_bound[cta - 1][q + 2][0];
#pragma unroll
                        for (int c4 = 0; c4 < BD / 4; c4++) {
                            float4 v = __ldcg(gp + c4);
                            en2[c4 * 4 + 0] = v.x; en2[c4 * 4 + 1] = v.y;
                            en2[c4 * 4 + 2] = v.z; en2[c4 * 4 + 3] = v.w;
                        }
                    }
                    // validate block q; re-poll rare stragglers
                    const float* src = &g_bound[cta - 1][q][0];
#pragma unroll
                    for (int i = 0; i < BD; i++) {
                        if (e[i] < 0.0f) {
                            float v = ld_cg_volatile(src + i);
                            while (v < 0.0f) {
                                __nanosleep(20);
                                v = ld_cg_volatile(src + i);
                            }
                            e[i] = v;
                        }
                    }
                }
                // cta == 0: e stays BIGV
            } else {
                const float4* sp = (const float4*)&bdry[rpar][warp][0];
#pragma unroll
                for (int c4 = 0; c4 < BD / 4; c4++) {
                    float4 v = sp[c4];
                    e[c4 * 4 + 0] = v.x; e[c4 * 4 + 1] = v.y;
                    e[c4 * 4 + 2] = v.z; e[c4 * 4 + 3] = v.w;
                }
            }

            // ---- y window: cell (i,k) uses yblk[RPT + i - k] ----
            float yblk[BD + RPT];
            {
                const float4* yp4 = (const float4*)&ypad[OFF + d0 - r0 - RPT];
#pragma unroll
                for (int c4 = 0; c4 < (BD + RPT) / 4; c4++) {
                    float4 v = yp4[c4];
                    yblk[c4 * 4 + 0] = v.x; yblk[c4 * 4 + 1] = v.y;
                    yblk[c4 * 4 + 2] = v.z; yblk[c4 * 4 + 3] = v.w;
                }
            }

            float* bps = &bdry[wpar][sprod ? warp + 1 : 0][0];  // smem target
            float* gq  = &g_bound[cta][q][0];                    // gmem target

            // Prime shfl pipeline: neighbor bottom b at d0-1 and d0-2.
            float nbb_cur = __shfl_up_sync(0xffffffffu, b[RPT - 1], 1);
            float nb_prev = __shfl_up_sync(0xffffffffu, a[RPT - 1], 1);

            // ---- BD diagonals; P = diag d-1 state, Q = d-2 -> d (in place).
            // k=RPT-1 first (independent of neighbor), then shfl for the
            // NEXT diagonal, then k=RPT-2..0 fill the shfl shadow.
#define DIAG_STEP(I, P, Q) do {                                            \
            float up0 = isl0 ? ((I) >= 1 ? e[(I) - 1] : cb) : nbb_cur;     \
            float dg0 = isl0 ? ((I) >= 2 ? e[(I) - 2]                      \
                                         : ((I) == 1 ? cb : ca))           \
                             : nb_prev;                                    \
            {                                                              \
                float cc = xs[RPT - 1] - yblk[(I) + 1];                    \
                Q[RPT - 1] = fmaf(cc, cc,                                  \
                    fminf(fminf(P[RPT - 2], P[RPT - 1]), Q[RPT - 2]));     \
            }                                                              \
            float nbb_next = __shfl_up_sync(0xffffffffu, Q[RPT - 1], 1);   \
            _Pragma("unroll")                                              \
            for (int k = RPT - 2; k >= 1; k--) {                           \
                float cc = xs[k] - yblk[RPT + (I) - k];                    \
                Q[k] = fmaf(cc, cc,                                        \
                    fminf(fminf(P[k - 1], P[k]), Q[k - 1]));               \
            }                                                              \
            {                                                              \
                float cc = xs[0] - yblk[RPT + (I)];                        \
                Q[0] = fmaf(cc, cc, fminf(fminf(up0, P[0]), dg0));         \
            }                                                              \
            if (sprod) { if (isl31) bps[(I)] = Q[RPT - 1]; }               \
            else if (gprod) { if (isl31) st_cg(gq + (I), Q[RPT - 1]); }    \
            if ((I) == 29) {                                               \
                if (qlast && wlast) out[0] = sqrtf(Q[RPT - 1]);            \
            }                                                              \
            nb_prev = nbb_cur; nbb_cur = nbb_next;                         \
        } while (0)

#define DIAG_PAIR(I) DIAG_STEP(I, b, a); DIAG_STEP((I) + 1, a, b)

            DIAG_PAIR(0);  DIAG_PAIR(2);  DIAG_PAIR(4);  DIAG_PAIR(6);
            DIAG_PAIR(8);  DIAG_PAIR(10); DIAG_PAIR(12); DIAG_PAIR(14);
            DIAG_PAIR(16); DIAG_PAIR(18); DIAG_PAIR(20); DIAG_PAIR(22);
            DIAG_PAIR(24); DIAG_PAIR(26); DIAG_PAIR(28); DIAG_PAIR(30);

#undef DIAG_PAIR
#undef DIAG_STEP

            // carries for next block: upstream bottom at d0+BD-1, d0+BD-2
            ca = e[BD - 2];
            cb = e[BD - 1];

            // rotate prefetch pipeline: e <- q+1, en <- q+2
            if (gcons) {
#pragma unroll
                for (int i = 0; i < BD; i++) { e[i] = en[i]; en[i] = en2[i]; }
            }
        }

        __syncthreads();
    }
}

extern "C" void kernel_launch(void* const* d_in, const int* in_sizes, int n_in,
                              void* d_out, int out_size)
{
    const float* x = (const float*)d_in[0];
    const float* y = (const float*)d_in[1];
    float* out = (float*)d_out;
    (void)in_sizes; (void)n_in; (void)out_size;
    reset_bound_kernel<<<32, 512>>>();
    dtw_wavefront<<<C, NT>>>(x, y, out);
}